// round 16
// baseline (speedup 1.0000x reference)
#include <cuda_runtime.h>
#include <cuda_fp16.h>

#define NN 1000000
#define NE 8000000
#define NEG_SLOPE 0.01f
#define CAP 96                    // bucket capacity; deg ~ Poisson(8), P(deg>=96) < 1e-60
#define NFILL ((NE / 4 + 255) / 256)      // 7813
#define NPROJB ((NN + 255) / 256)         // 3907 blocks x 256 nodes

// Scratch (device globals — no runtime allocation allowed).
__device__ __half g_h16[(size_t)NN * 64];      // projected features, fp16: [N][64]
__device__ int    g_cnt[NN];                   // per-row edge count (zeroed by k_row)
__device__ int    g_bucket[(size_t)NN * CAP];  // per-row column buckets

// ---- packed f32x2 helpers (sm_103a FFMA2; rn per half == scalar FFMA) ----
#define PACK2(out, lo, hi) \
    asm("mov.b64 %0, {%1, %2};" : "=l"(out) : "f"(lo), "f"(hi))
#define UNPACK2(lo, hi, in) \
    asm("mov.b64 {%0, %1}, %2;" : "=f"(lo), "=f"(hi) : "l"(in))
#define FMA2(acc, a, b) \
    asm("fma.rn.f32x2 %0, %1, %2, %0;" : "+l"(acc) : "l"(a), "l"(b))

// shared layout (dynamic): sX [64][260] fp32 transposed+swizzled x,
// sW2 [64][66] b64 splatted (w,w), sB2 [64] b64 splatted bias.
#define SX_STRIDE 260
#define SX_BYTES  (64 * SX_STRIDE * 4)        // 66560
#define SW2_OFF   SX_BYTES
#define SW2_BYTES (64 * 66 * 8)               // 33792
#define SB2_OFF   (SW2_OFF + SW2_BYTES)
#define SMEM_PROJ (SB2_OFF + 64 * 8)          // 100864

// tiny pad kernel: shifts launch order so the profiler's fixed 4th-launch
// sample lands on k_row.
__global__ void k_pad() {}

// -------------------- projection: register-tiled GEMM --------------------
// Block: 256 threads = 32 tcol (8 nodes each) x 8 trow (8 dims each); 256 nodes.
// Thread computes an 8-node x 8-dim tile: per k-step 2 a-LDS.128 + 4 b-LDS.128
// feed 32 FFMA2 (64 MACs) -> 4 MACs per LDS-float (vs 1 in the old form).
// sX is stored transposed [k][node] with node-group XOR swizzle g' = g ^ ((k>>2)&7)
// (g = node>>2) so the staging writes are ~2-way instead of 16-way conflicted
// while a-loads stay 16B-aligned and conflict-free.
// Output: fp16 h only (k_row consumes fp16 everywhere now).
__global__ void __launch_bounds__(256, 2) k_project(const float* __restrict__ ego,
                                                    const float* __restrict__ W,
                                                    const float* __restrict__ b) {
    extern __shared__ char smem[];
    float* sX = (float*)smem;
    unsigned long long* sW2 = (unsigned long long*)(smem + SW2_OFF);
    unsigned long long* sB2 = (unsigned long long*)(smem + SB2_OFF);

    int t = threadIdx.x;
    int base = blockIdx.x * 256;

    // stage W as splatted (w,w) pairs: sW2[k][D], D = c*32+d
    for (int i = t; i < 4096; i += 256) {
        float w = W[i];
        int k = (i >> 5) & 63;
        int D = ((i >> 11) << 5) | (i & 31);
        unsigned long long ww; PACK2(ww, w, w);
        sW2[k * 66 + D] = ww;
    }
    if (t < 64) {
        float bb = b[t];
        unsigned long long b2; PACK2(b2, bb, bb);
        sB2[t] = b2;
    }
    // stage x transposed+swizzled: element (node,k) -> sX[k][node ^ 4*((k>>2)&7)]
    const float4* egob = (const float4*)(ego + (size_t)base * 64);
#pragma unroll
    for (int j = 0; j < 16; j++) {
        int idx4 = j * 256 + t;
        int node = idx4 >> 4;
        int kq = idx4 & 15;                  // k = 4*kq .. 4*kq+3, s = kq&7
        float4 v = make_float4(0.f, 0.f, 0.f, 0.f);
        if (base + node < NN) v = egob[idx4];
        int nswz = node ^ (4 * (kq & 7));
        sX[(kq*4 + 0) * SX_STRIDE + nswz] = v.x;
        sX[(kq*4 + 1) * SX_STRIDE + nswz] = v.y;
        sX[(kq*4 + 2) * SX_STRIDE + nswz] = v.z;
        sX[(kq*4 + 3) * SX_STRIDE + nswz] = v.w;
    }
    __syncthreads();

    int tcol = t >> 3;        // node group-of-8: nodes tcol*8 .. +8
    int trow = t & 7;         // dim group-of-8:  dims trow*8 .. +8
    int gA = tcol * 2;        // node quad indices gA, gA+1

    unsigned long long acc[4][8];   // [node pair][dim], pair p = nodes (2p,2p+1)
#pragma unroll
    for (int d = 0; d < 8; d++) {
        unsigned long long bb = sB2[trow * 8 + d];
        acc[0][d] = bb; acc[1][d] = bb; acc[2][d] = bb; acc[3][d] = bb;
    }

    for (int kk = 0; kk < 16; kk++) {        // 4 k per group, s constant in group
        int s = kk & 7;
        int offA = ((gA ^ s) << 2);
        int offB = (((gA + 1) ^ s) << 2);
        const unsigned long long* wrow = &sW2[(kk * 4) * 66 + trow * 8];
#pragma unroll
        for (int j = 0; j < 4; j++) {
            int k = kk * 4 + j;
            ulonglong2 aA = *(const ulonglong2*)&sX[k * SX_STRIDE + offA];
            ulonglong2 aB = *(const ulonglong2*)&sX[k * SX_STRIDE + offB];
            const ulonglong2* bp = (const ulonglong2*)(wrow + (size_t)j * 66);
            ulonglong2 b01 = bp[0], b23 = bp[1], b45 = bp[2], b67 = bp[3];
            unsigned long long bv[8] = {b01.x, b01.y, b23.x, b23.y,
                                        b45.x, b45.y, b67.x, b67.y};
#pragma unroll
            for (int d = 0; d < 8; d++) {
                FMA2(acc[0][d], aA.x, bv[d]);
                FMA2(acc[1][d], aA.y, bv[d]);
                FMA2(acc[2][d], aB.x, bv[d]);
                FMA2(acc[3][d], aB.y, bv[d]);
            }
        }
    }

    // epilogue: leaky + fp16 store; thread writes dims trow*8..+8 of 8 nodes
#pragma unroll
    for (int p = 0; p < 4; p++) {
#pragma unroll
        for (int half = 0; half < 2; half++) {
            int node = base + tcol * 8 + 2 * p + half;
            if (node >= NN) continue;
            float f[8];
#pragma unroll
            for (int d = 0; d < 8; d++) {
                float lo, hi;
                UNPACK2(lo, hi, acc[p][d]);
                float val = half ? hi : lo;
                f[d] = fmaxf(val, NEG_SLOPE * val);
            }
            __half2 q0 = __floats2half2_rn(f[0], f[1]);
            __half2 q1 = __floats2half2_rn(f[2], f[3]);
            __half2 q2 = __floats2half2_rn(f[4], f[5]);
            __half2 q3 = __floats2half2_rn(f[6], f[7]);
            uint4 pack;
            pack.x = *(unsigned*)&q0; pack.y = *(unsigned*)&q1;
            pack.z = *(unsigned*)&q2; pack.w = *(unsigned*)&q3;
            *(uint4*)(g_h16 + (size_t)node * 64 + trow * 8) = pack;
        }
    }
}

// -------------------- bucket fill --------------------
__global__ void __launch_bounds__(256) k_fill(const int* __restrict__ row,
                                              const int* __restrict__ col) {
    int e4 = blockIdx.x * 256 + threadIdx.x;
    if (e4 < NE / 4) {
        int4 r = ((const int4*)row)[e4];
        int4 c = ((const int4*)col)[e4];
        int s;
        s = atomicAdd(&g_cnt[r.x], 1); if (s < CAP) g_bucket[(size_t)r.x * CAP + s] = c.x;
        s = atomicAdd(&g_cnt[r.y], 1); if (s < CAP) g_bucket[(size_t)r.y * CAP + s] = c.y;
        s = atomicAdd(&g_cnt[r.z], 1); if (s < CAP) g_bucket[(size_t)r.z * CAP + s] = c.z;
        s = atomicAdd(&g_cnt[r.w], 1); if (s < CAP) g_bucket[(size_t)r.w * CAP + s] = c.w;
    }
}

// -------------------- fused softmax + aggregation --------------------
// One warp per row, FOUR edge slots: slot = lane>>3 handles edge i+slot;
// l8 = lane&7 owns dims [8*l8, 8*l8+8) (fp16, one LDG.128 per lane per iter
// -> 128B/edge, MLP_p1 = 1). Dot reduce = 2 shfl.xor (1,2) within the 4-lane
// channel group; lanes l8<4 hold channel 0, l8>=4 channel 1, so each lane
// computes its own channel's exp locally — no cross-channel traffic. Cross-
// slot reduction (xor 8,16) happens once per ROW. ~7 warp-instrs/edge vs ~13.
// segment_max dropped: logits bounded (<~60) so exp cannot overflow fp32,
// and sum(exp) >= exp(max) keeps EPS negligible exactly as in the reference.
// After consuming g_cnt[r], lane 0 resets it (replay-idempotent).
__global__ void __launch_bounds__(256) k_row(float* __restrict__ out) {
    int w = (blockIdx.x * 256 + threadIdx.x) >> 5;
    int lane = threadIdx.x & 31;
    if (w >= NN) return;
    int slot = lane >> 3;
    int l8 = lane & 7;

    int n = g_cnt[w];
    if (n > CAP) n = CAP;
    const int* bkt = g_bucket + (size_t)w * CAP;

    uint4 hraw = *(const uint4*)(g_h16 + (size_t)w * 64 + l8 * 8);
    float2 h01 = __half22float2(*(__half2*)&hraw.x);
    float2 h23 = __half22float2(*(__half2*)&hraw.y);
    float2 h45 = __half22float2(*(__half2*)&hraw.z);
    float2 h67 = __half22float2(*(__half2*)&hraw.w);

    float a0 = 0.f, a1 = 0.f, a2 = 0.f, a3 = 0.f;
    float a4 = 0.f, a5 = 0.f, a6 = 0.f, a7 = 0.f;
    float dsum = 0.f;

    for (int i = 0; i < n; i += 4) {
        int j = i + slot;
        bool valid = j < n;
        int c = valid ? bkt[j] : 0;
        uint4 raw = *(const uint4*)(g_h16 + (size_t)c * 64 + l8 * 8);
        float2 v01 = __half22float2(*(__half2*)&raw.x);
        float2 v23 = __half22float2(*(__half2*)&raw.y);
        float2 v45 = __half22float2(*(__half2*)&raw.z);
        float2 v67 = __half22float2(*(__half2*)&raw.w);
        float p = h01.x * v01.x + h01.y * v01.y + h23.x * v23.x + h23.y * v23.y
                + h45.x * v45.x + h45.y * v45.y + h67.x * v67.x + h67.y * v67.y;
        p += __shfl_xor_sync(0xffffffffu, p, 1);
        p += __shfl_xor_sync(0xffffffffu, p, 2);
        p = fmaxf(p, NEG_SLOPE * p);
        float ex = valid ? __expf(p) : 0.f;
        dsum += ex;
        a0 += ex * v01.x; a1 += ex * v01.y; a2 += ex * v23.x; a3 += ex * v23.y;
        a4 += ex * v45.x; a5 += ex * v45.y; a6 += ex * v67.x; a7 += ex * v67.y;
    }

#define RED2(x) x += __shfl_xor_sync(0xffffffffu, x, 8); \
                x += __shfl_xor_sync(0xffffffffu, x, 16);
    RED2(dsum)
    RED2(a0) RED2(a1) RED2(a2) RED2(a3)
    RED2(a4) RED2(a5) RED2(a6) RED2(a7)
#undef RED2

    float inv = 1.f / (dsum + 1e-10f);
    float acc2[8] = {a0, a1, a2, a3, a4, a5, a6, a7};
    float2 o = make_float2(acc2[2 * slot] * inv, acc2[2 * slot + 1] * inv);
    *(float2*)(out + (size_t)w * 64 + l8 * 8 + slot * 2) = o;

    if (lane == 0) g_cnt[w] = 0;   // replay-idempotent reset
}

extern "C" void kernel_launch(void* const* d_in, const int* in_sizes, int n_in,
                              void* d_out, int out_size) {
    const float* ego = (const float*)d_in[0];
    const float* W   = (const float*)d_in[1];
    const float* b   = (const float*)d_in[2];
    const int*   row = (const int*)d_in[3];
    const int*   col = (const int*)d_in[4];
    float* out = (float*)d_out;

    static int smem_set = 0;
    cudaFuncSetAttribute(k_project, cudaFuncAttributeMaxDynamicSharedMemorySize,
                         SMEM_PROJ);
    (void)smem_set;

    // 4 launches/replay: pad, project, fill, row -> profiler's 4th launch = k_row.
    k_pad<<<1, 32>>>();
    k_project<<<NPROJB, 256, SMEM_PROJ>>>(ego, W, b);
    k_fill<<<NFILL, 256>>>(row, col);
    k_row<<<(NN * 32 + 255) / 256, 256>>>(out);
}